// round 5
// baseline (speedup 1.0000x reference)
#include <cuda_runtime.h>
#include <cuda_fp16.h>
#include <math.h>

#define NMAX 100000
#define EMAX 1600000

// ---------------- scratch (device globals; zero-initialized at load) ---------
__device__ __half g_h1h[NMAX * 128];   // layer1 features, fp16 (gather payload)
__device__ __half g_h2h[NMAX * 64];    // layer2 features, fp16
__device__ float  g_as1[NMAX * 8];
__device__ float  g_ad1[NMAX * 8];
__device__ float  g_x2[NMAX * 128];    // elu(out1+b1), fp32 (gemm2 input)
__device__ float  g_as2[NMAX];
__device__ float  g_ad2[NMAX];
__device__ int    g_cnt[NMAX];         // histogram   (left zeroed by gat1)
__device__ int    g_cnt2[NMAX];        // scatter fill counter -> degree (zeroed by gat2)
__device__ int    g_fillbase[NMAX];    // local exclusive prefix within scan block
__device__ int    g_srcs[EMAX];
__device__ int    g_bsum[512];
__device__ int    g_boff[512];

__device__ __forceinline__ float lrelu(float x) { return x > 0.f ? x : 0.2f * x; }
__device__ __forceinline__ float elu1(float x)  { return x > 0.f ? x : (__expf(x) - 1.f); }

__device__ __forceinline__ unsigned long long pack2b(float x) {
    unsigned long long r;
    asm("mov.b64 %0, {%1, %1};" : "=l"(r) : "f"(x));
    return r;
}
__device__ __forceinline__ unsigned long long pack2f(float x, float y) {
    unsigned long long r;
    asm("mov.b64 %0, {%1, %2};" : "=l"(r) : "f"(x), "f"(y));
    return r;
}
__device__ __forceinline__ void ffma2(unsigned long long& d, unsigned long long a, unsigned long long b) {
    asm("fma.rn.f32x2 %0, %1, %2, %0;" : "+l"(d) : "l"(a), "l"(b));
}
__device__ __forceinline__ void unpack2(unsigned long long p, float& lo, float& hi) {
    asm("mov.b64 {%0, %1}, %2;" : "=f"(lo), "=f"(hi) : "l"(p));
}

// ---------------- CSR build ---------------------------------------------------
__global__ void hist_kernel(const int* __restrict__ ei, int e) {
    int i = blockIdx.x * blockDim.x + threadIdx.x;
    if (i < e) atomicAdd(&g_cnt[ei[e + i]], 1);
}

// per-block inclusive scan; writes local exclusive prefix + block totals
__global__ void scan1_kernel(int n) {
    __shared__ int wsum[32];
    int t = threadIdx.x, lane = t & 31, wid = t >> 5;
    int i = blockIdx.x * 1024 + t;
    int v = (i < n) ? g_cnt[i] : 0;
    int x = v;
    #pragma unroll
    for (int off = 1; off < 32; off <<= 1) {
        int u = __shfl_up_sync(0xffffffffu, x, off);
        if (lane >= off) x += u;
    }
    if (lane == 31) wsum[wid] = x;
    __syncthreads();
    if (wid == 0) {
        int s = wsum[lane];
        #pragma unroll
        for (int off = 1; off < 32; off <<= 1) {
            int u = __shfl_up_sync(0xffffffffu, s, off);
            if (lane >= off) s += u;
        }
        wsum[lane] = s;
    }
    __syncthreads();
    int incl = x + (wid ? wsum[wid - 1] : 0);
    if (i < n) g_fillbase[i] = incl - v;      // local exclusive prefix
    if (t == 1023) g_bsum[blockIdx.x] = incl;
}

__global__ void scan2_kernel(int nb) {
    __shared__ int wsum[32];
    int t = threadIdx.x, lane = t & 31, wid = t >> 5;
    int v = (t < nb) ? g_bsum[t] : 0;
    int x = v;
    #pragma unroll
    for (int off = 1; off < 32; off <<= 1) {
        int u = __shfl_up_sync(0xffffffffu, x, off);
        if (lane >= off) x += u;
    }
    if (lane == 31) wsum[wid] = x;
    __syncthreads();
    if (wid == 0) {
        int s = wsum[lane];
        #pragma unroll
        for (int off = 1; off < 32; off <<= 1) {
            int u = __shfl_up_sync(0xffffffffu, s, off);
            if (lane >= off) s += u;
        }
        wsum[lane] = s;
    }
    __syncthreads();
    int incl = x + (wid ? wsum[wid - 1] : 0);
    if (t < nb) g_boff[t] = incl - v;
}

__global__ void scatter_kernel(const int* __restrict__ ei, int e) {
    int i = blockIdx.x * blockDim.x + threadIdx.x;
    if (i < e) {
        int s = ei[i];
        int d = ei[e + i];
        int base = g_fillbase[d] + g_boff[d >> 10];
        int pos = base + atomicAdd(&g_cnt2[d], 1);
        g_srcs[pos] = s;
    }
}

// ---------------- GEMM1 + att1 fold: h1h = fp16(x@W1); as1/ad1 ---------------
__global__ void gemm1_kernel(const float* __restrict__ A, const float* __restrict__ B,
                             const float* __restrict__ att_s, const float* __restrict__ att_d,
                             int M) {
    const int K = 256, NC = 128;
    __shared__ float As[32][65];
    __shared__ float Bs[32][128];
    int tid = threadIdx.x;
    int blockRow = blockIdx.x * 64;
    int aRow = tid >> 3;
    int aCol = (tid & 7) << 2;
    int bRow = tid >> 5;
    int bCol = (tid & 31) << 2;
    int tRow = (tid >> 4) << 2;
    int tCol = (tid & 15) << 3;
    unsigned long long acc[4][4];
    #pragma unroll
    for (int i = 0; i < 4; i++)
        #pragma unroll
        for (int j = 0; j < 4; j++) acc[i][j] = 0ull;

    for (int k0 = 0; k0 < K; k0 += 32) {
        #pragma unroll
        for (int r = 0; r < 2; r++) {
            int row = blockRow + aRow + r * 32;
            float4 v = (row < M) ? *(const float4*)(A + (size_t)row * K + k0 + aCol)
                                 : make_float4(0.f, 0.f, 0.f, 0.f);
            As[aCol + 0][aRow + r * 32] = v.x;
            As[aCol + 1][aRow + r * 32] = v.y;
            As[aCol + 2][aRow + r * 32] = v.z;
            As[aCol + 3][aRow + r * 32] = v.w;
        }
        #pragma unroll
        for (int r = 0; r < 4; r++) {
            int row = bRow + r * 8;
            *(float4*)&Bs[row][bCol] = *(const float4*)(B + (size_t)(k0 + row) * NC + bCol);
        }
        __syncthreads();
        #pragma unroll
        for (int k = 0; k < 32; k++) {
            unsigned long long ap[4];
            ap[0] = pack2b(As[k][tRow]);
            ap[1] = pack2b(As[k][tRow + 1]);
            ap[2] = pack2b(As[k][tRow + 2]);
            ap[3] = pack2b(As[k][tRow + 3]);
            float4 bv0 = *(float4*)&Bs[k][tCol];
            float4 bv1 = *(float4*)&Bs[k][tCol + 4];
            unsigned long long bp[4];
            bp[0] = pack2f(bv0.x, bv0.y);
            bp[1] = pack2f(bv0.z, bv0.w);
            bp[2] = pack2f(bv1.x, bv1.y);
            bp[3] = pack2f(bv1.z, bv1.w);
            #pragma unroll
            for (int i = 0; i < 4; i++)
                #pragma unroll
                for (int j = 0; j < 4; j++) ffma2(acc[i][j], ap[i], bp[j]);
        }
        __syncthreads();
    }

    int hd = tCol >> 4;
    int co = tCol & 15;
    float as_v[8], ad_v[8];
    #pragma unroll
    for (int j = 0; j < 8; j++) {
        as_v[j] = __ldg(&att_s[hd * 16 + co + j]);
        ad_v[j] = __ldg(&att_d[hd * 16 + co + j]);
    }
    #pragma unroll
    for (int i = 0; i < 4; i++) {
        int row = blockRow + tRow + i;
        float o[8];
        #pragma unroll
        for (int j = 0; j < 4; j++) unpack2(acc[i][j], o[2 * j], o[2 * j + 1]);
        __half hb[8];
        #pragma unroll
        for (int j = 0; j < 8; j++) hb[j] = __float2half_rn(o[j]);
        float s = 0.f, d = 0.f;
        #pragma unroll
        for (int j = 0; j < 8; j++) { s += o[j] * as_v[j]; d += o[j] * ad_v[j]; }
        s += __shfl_xor_sync(0xffffffffu, s, 1);
        d += __shfl_xor_sync(0xffffffffu, d, 1);
        if (row < M) {
            *(uint4*)&g_h1h[(size_t)row * 128 + tCol] = *(uint4*)hb;
            if ((tid & 1) == 0) {
                g_as1[row * 8 + hd] = s;
                g_ad1[row * 8 + hd] = d;
            }
        }
    }
}

// ---------------- layer-1 gather: TWO warps per node -------------------------
__global__ void gat1_kernel(const float* __restrict__ b1, int n) {
    __shared__ float s_acc[4][128];
    __shared__ float s_den[4][8];
    int node = (blockIdx.x * blockDim.x + threadIdx.x) >> 6;
    int half = (threadIdx.x >> 5) & 1;
    int lp   = threadIdx.x >> 6;          // local pair 0..3
    int lid  = threadIdx.x & 31;
    bool live = node < n;
    int base0 = 0, deg = 0;
    if (live) {
        base0 = g_fillbase[node] + g_boff[node >> 10];
        deg   = g_cnt2[node];
    }
    int h0 = (deg + 1) >> 1;
    int beg = base0 + (half ? h0 : 0);
    int end = base0 + (half ? deg : h0);

    int h  = lid >> 2;
    int eo = lid >> 3;
    int hh = lid & 7;
    float adl = live ? g_ad1[node * 8 + hh] : 0.f;
    float4 acc = make_float4(0.f, 0.f, 0.f, 0.f);
    float dpart = 0.f;

    for (int base = beg; base < end; base += 32) {
        int cnt = end - base; if (cnt > 32) cnt = 32;
        int sidx = (base + lid < end) ? __ldg(&g_srcs[base + lid]) : 0;
        for (int g = 0; g < cnt; g += 4) {
            int sj = __shfl_sync(0xffffffffu, sidx, g + eo);
            float w = 0.f;
            if (g + eo < cnt)
                w = __expf(lrelu(__ldg(&g_as1[sj * 8 + hh]) + adl));
            dpart += w;
            #pragma unroll
            for (int q = 0; q < 4; q++) {
                float wq = __shfl_sync(0xffffffffu, w, q * 8 + h);
                int   sq = __shfl_sync(0xffffffffu, sidx, g + q);
                uint2 hv = *(const uint2*)&g_h1h[(size_t)sq * 128 + lid * 4];
                float2 f0 = __half22float2(*(__half2*)&hv.x);
                float2 f1 = __half22float2(*(__half2*)&hv.y);
                acc.x += wq * f0.x;
                acc.y += wq * f0.y;
                acc.z += wq * f1.x;
                acc.w += wq * f1.y;
            }
        }
    }
    // per-warp denominator reduce: lane L (<8) ends holding head L's sum
    float dsum = dpart;
    dsum += __shfl_xor_sync(0xffffffffu, dsum, 8);
    dsum += __shfl_xor_sync(0xffffffffu, dsum, 16);

    if (half == 1) {
        *(float4*)&s_acc[lp][lid * 4] = acc;
        if (lid < 8) s_den[lp][lid] = dsum;
    }
    __syncthreads();
    if (half == 0 && live) {
        float4 oa = *(float4*)&s_acc[lp][lid * 4];
        acc.x += oa.x; acc.y += oa.y; acc.z += oa.z; acc.w += oa.w;
        float dh = __shfl_sync(0xffffffffu, dsum, h) + s_den[lp][h];
        float inv = 1.f / (dh + 1e-16f);
        float4 bb = *(const float4*)&b1[lid * 4];
        float4 o;
        o.x = elu1(acc.x * inv + bb.x);
        o.y = elu1(acc.y * inv + bb.y);
        o.z = elu1(acc.z * inv + bb.z);
        o.w = elu1(acc.w * inv + bb.w);
        *(float4*)&g_x2[(size_t)node * 128 + lid * 4] = o;
        if (lid == 0) g_cnt[node] = 0;    // reset histogram for next replay
    }
}

// ---------------- GEMM2 + att2 fold: h2h = fp16(x2@W2); as2/ad2 --------------
__global__ void gemm2_kernel(const float* __restrict__ B,
                             const float* __restrict__ att_s, const float* __restrict__ att_d,
                             int M) {
    const int K = 128, NC = 64;
    __shared__ float As[32][65];
    __shared__ float Bs[32][64];
    int tid = threadIdx.x;
    int blockRow = blockIdx.x * 64;
    int aRow = tid >> 3;
    int aCol = (tid & 7) << 2;
    int bRow = tid >> 4;
    int bCol = (tid & 15) << 2;
    int tRow = (tid >> 4) << 2;
    int tCol = (tid & 15) << 2;
    const float* A = g_x2;
    unsigned long long acc[4][2];
    #pragma unroll
    for (int i = 0; i < 4; i++) { acc[i][0] = 0ull; acc[i][1] = 0ull; }

    for (int k0 = 0; k0 < K; k0 += 32) {
        #pragma unroll
        for (int r = 0; r < 2; r++) {
            int row = blockRow + aRow + r * 32;
            float4 v = (row < M) ? *(const float4*)(A + (size_t)row * K + k0 + aCol)
                                 : make_float4(0.f, 0.f, 0.f, 0.f);
            As[aCol + 0][aRow + r * 32] = v.x;
            As[aCol + 1][aRow + r * 32] = v.y;
            As[aCol + 2][aRow + r * 32] = v.z;
            As[aCol + 3][aRow + r * 32] = v.w;
        }
        #pragma unroll
        for (int r = 0; r < 2; r++) {
            int row = bRow + r * 16;
            *(float4*)&Bs[row][bCol] = *(const float4*)(B + (size_t)(k0 + row) * NC + bCol);
        }
        __syncthreads();
        #pragma unroll
        for (int k = 0; k < 32; k++) {
            unsigned long long ap[4];
            ap[0] = pack2b(As[k][tRow]);
            ap[1] = pack2b(As[k][tRow + 1]);
            ap[2] = pack2b(As[k][tRow + 2]);
            ap[3] = pack2b(As[k][tRow + 3]);
            float4 bv = *(float4*)&Bs[k][tCol];
            unsigned long long bp0 = pack2f(bv.x, bv.y);
            unsigned long long bp1 = pack2f(bv.z, bv.w);
            #pragma unroll
            for (int i = 0; i < 4; i++) { ffma2(acc[i][0], ap[i], bp0); ffma2(acc[i][1], ap[i], bp1); }
        }
        __syncthreads();
    }

    float as_v[4], ad_v[4];
    #pragma unroll
    for (int j = 0; j < 4; j++) {
        as_v[j] = __ldg(&att_s[tCol + j]);
        ad_v[j] = __ldg(&att_d[tCol + j]);
    }
    #pragma unroll
    for (int i = 0; i < 4; i++) {
        int row = blockRow + tRow + i;
        float o[4];
        unpack2(acc[i][0], o[0], o[1]);
        unpack2(acc[i][1], o[2], o[3]);
        __half hb[4];
        #pragma unroll
        for (int j = 0; j < 4; j++) hb[j] = __float2half_rn(o[j]);
        float s = 0.f, d = 0.f;
        #pragma unroll
        for (int j = 0; j < 4; j++) { s += o[j] * as_v[j]; d += o[j] * ad_v[j]; }
        #pragma unroll
        for (int off = 1; off < 16; off <<= 1) {
            s += __shfl_xor_sync(0xffffffffu, s, off);
            d += __shfl_xor_sync(0xffffffffu, d, off);
        }
        if (row < M) {
            *(uint2*)&g_h2h[(size_t)row * 64 + tCol] = *(uint2*)hb;
            if ((tid & 15) == 0) {
                g_as2[row] = s;
                g_ad2[row] = d;
            }
        }
    }
}

// ---------------- layer-2 gather: TWO warps per node + log_softmax -----------
__global__ void gat2_kernel(const float* __restrict__ b2, float* __restrict__ out, int n) {
    __shared__ float s_acc[4][64];
    __shared__ float s_den[4];
    int node = (blockIdx.x * blockDim.x + threadIdx.x) >> 6;
    int half = (threadIdx.x >> 5) & 1;
    int lp   = threadIdx.x >> 6;
    int lid  = threadIdx.x & 31;
    bool live = node < n;
    int base0 = 0, deg = 0;
    if (live) {
        base0 = g_fillbase[node] + g_boff[node >> 10];
        deg   = g_cnt2[node];
    }
    int h0 = (deg + 1) >> 1;
    int beg = base0 + (half ? h0 : 0);
    int end = base0 + (half ? deg : h0);
    float adn = live ? g_ad2[node] : 0.f;

    float acc0 = 0.f, acc1 = 0.f, dpart = 0.f;
    for (int base = beg; base < end; base += 32) {
        int cnt = end - base; if (cnt > 32) cnt = 32;
        int sidx = (base + lid < end) ? __ldg(&g_srcs[base + lid]) : 0;
        for (int g = 0; g < cnt; g += 4) {
            int widx = g + (lid & 3); if (widx > 31) widx = 31;
            int sj = __shfl_sync(0xffffffffu, sidx, widx);
            float w = 0.f;
            if (lid < 4 && g + lid < cnt)
                w = __expf(lrelu(__ldg(&g_as2[sj]) + adn));
            dpart += w;
            #pragma unroll
            for (int q = 0; q < 4; q++) {
                float wq = __shfl_sync(0xffffffffu, w, q);
                int   sq = __shfl_sync(0xffffffffu, sidx, g + q);
                __half2 hv = *(const __half2*)&g_h2h[(size_t)sq * 64 + lid * 2];
                float2 v = __half22float2(hv);
                acc0 += wq * v.x;
                acc1 += wq * v.y;
            }
        }
    }
    float dsum = dpart;
    dsum += __shfl_xor_sync(0xffffffffu, dsum, 1);
    dsum += __shfl_xor_sync(0xffffffffu, dsum, 2);
    float dt = __shfl_sync(0xffffffffu, dsum, 0);

    if (half == 1) {
        s_acc[lp][lid * 2]     = acc0;
        s_acc[lp][lid * 2 + 1] = acc1;
        if (lid == 0) s_den[lp] = dt;
    }
    __syncthreads();
    if (half == 0 && live) {
        acc0 += s_acc[lp][lid * 2];
        acc1 += s_acc[lp][lid * 2 + 1];
        dt += s_den[lp];
        float inv = 1.f / (dt + 1e-16f);
        float o0 = acc0 * inv + __ldg(&b2[lid * 2]);
        float o1 = acc1 * inv + __ldg(&b2[lid * 2 + 1]);

        float rm = fmaxf(o0, o1);
        #pragma unroll
        for (int off = 16; off; off >>= 1)
            rm = fmaxf(rm, __shfl_xor_sync(0xffffffffu, rm, off));
        float se = __expf(o0 - rm) + __expf(o1 - rm);
        #pragma unroll
        for (int off = 16; off; off >>= 1)
            se += __shfl_xor_sync(0xffffffffu, se, off);
        float lse = rm + __logf(se);

        float2 res;
        res.x = o0 - lse;
        res.y = o1 - lse;
        *(float2*)&out[(size_t)node * 64 + lid * 2] = res;
        if (lid == 0) g_cnt2[node] = 0;   // reset degree counter for next replay
    }
}

// ---------------- launch ------------------------------------------------------
extern "C" void kernel_launch(void* const* d_in, const int* in_sizes, int n_in,
                              void* d_out, int out_size) {
    const float* x      = (const float*)d_in[0];
    const int*   ei     = (const int*)d_in[1];
    const float* W1     = (const float*)d_in[2];
    const float* att1_s = (const float*)d_in[3];
    const float* att1_d = (const float*)d_in[4];
    const float* b1     = (const float*)d_in[5];
    const float* W2     = (const float*)d_in[6];
    const float* att2_s = (const float*)d_in[7];
    const float* att2_d = (const float*)d_in[8];
    const float* b2     = (const float*)d_in[9];
    float* out = (float*)d_out;

    int n = in_sizes[0] / 256;
    int e = in_sizes[1] / 2;
    int nb = (n + 1023) / 1024;

    static cudaStream_t s2 = nullptr;
    static cudaEvent_t evFork = nullptr, evJoin = nullptr;
    if (!s2) {
        cudaStreamCreateWithFlags(&s2, cudaStreamNonBlocking);
        cudaEventCreateWithFlags(&evFork, cudaEventDisableTiming);
        cudaEventCreateWithFlags(&evJoin, cudaEventDisableTiming);
    }

    // fork: gemm1 (+folded att1) concurrent with CSR build   [launch 0]
    cudaEventRecord(evFork, 0);
    cudaStreamWaitEvent(s2, evFork, 0);
    gemm1_kernel<<<(n + 63) / 64, 256, 0, s2>>>(x, W1, att1_s, att1_d, n);
    cudaEventRecord(evJoin, s2);

    // CSR build on the main stream                           [launches 1-4]
    hist_kernel<<<(e + 255) / 256, 256>>>(ei, e);
    scan1_kernel<<<nb, 1024>>>(n);
    scan2_kernel<<<1, 512>>>(nb);
    scatter_kernel<<<(e + 255) / 256, 256>>>(ei, e);

    // join, then the dependent chain                          [launch 5 = gat1]
    cudaStreamWaitEvent(0, evJoin, 0);
    gat1_kernel<<<(n * 2 + 7) / 8, 256>>>(b1, n);
    gemm2_kernel<<<(n + 63) / 64, 256>>>(W2, att2_s, att2_d, n);
    gat2_kernel<<<(n * 2 + 7) / 8, 256>>>(b2, out, n);
}

// round 10
// speedup vs baseline: 1.9050x; 1.9050x over previous
#include <cuda_runtime.h>
#include <cuda_fp16.h>
#include <mma.h>
#include <math.h>
#include <stdint.h>

using namespace nvcuda;

#define NMAX 100000
#define EMAX 1600000

__device__ __half g_h1h[NMAX * 128];
__device__ __half g_x2h[NMAX * 128];
__device__ __half g_h2h[NMAX * 64];
__device__ float  g_as1[NMAX * 8];
__device__ float  g_ad1[NMAX * 8];
__device__ float  g_as2[NMAX];
__device__ float  g_ad2[NMAX];
__device__ int    g_cnt[NMAX];
__device__ int    g_cnt2[NMAX];
__device__ int    g_fillbase[NMAX];
__device__ int    g_srcs[EMAX];
__device__ int    g_bsum[512];
__device__ int    g_boff[512];

__device__ __forceinline__ float lrelu(float x) { return x > 0.f ? x : 0.2f * x; }
__device__ __forceinline__ float elu1(float x)  { return x > 0.f ? x : (__expf(x) - 1.f); }

// ---------------- CSR build ---------------------------------------------------
__global__ void hist_kernel(const int* __restrict__ ei, int e) {
    int i = blockIdx.x * blockDim.x + threadIdx.x;
    if (i < e) atomicAdd(&g_cnt[ei[e + i]], 1);
}

__global__ void scan1_kernel(int n) {
    __shared__ int wsum[32];
    int t = threadIdx.x;
    int lane = t & 31;
    int wid = t >> 5;
    int i = blockIdx.x * 1024 + t;
    int v = (i < n) ? g_cnt[i] : 0;
    int x = v;
    #pragma unroll
    for (int off = 1; off < 32; off <<= 1) {
        int u = __shfl_up_sync(0xffffffffu, x, off);
        if (lane >= off) x += u;
    }
    if (lane == 31) wsum[wid] = x;
    __syncthreads();
    if (wid == 0) {
        int s = wsum[lane];
        #pragma unroll
        for (int off = 1; off < 32; off <<= 1) {
            int u = __shfl_up_sync(0xffffffffu, s, off);
            if (lane >= off) s += u;
        }
        wsum[lane] = s;
    }
    __syncthreads();
    int incl = x + (wid ? wsum[wid - 1] : 0);
    if (i < n) g_fillbase[i] = incl - v;
    if (t == 1023) g_bsum[blockIdx.x] = incl;
}

__global__ void scan2_kernel(int nb) {
    __shared__ int wsum[32];
    int t = threadIdx.x;
    int lane = t & 31;
    int wid = t >> 5;
    int v = (t < nb) ? g_bsum[t] : 0;
    int x = v;
    #pragma unroll
    for (int off = 1; off < 32; off <<= 1) {
        int u = __shfl_up_sync(0xffffffffu, x, off);
        if (lane >= off) x += u;
    }
    if (lane == 31) wsum[wid] = x;
    __syncthreads();
    if (wid == 0) {
        int s = wsum[lane];
        #pragma unroll
        for (int off = 1; off < 32; off <<= 1) {
            int u = __shfl_up_sync(0xffffffffu, s, off);
            if (lane >= off) s += u;
        }
        wsum[lane] = s;
    }
    __syncthreads();
    int incl = x + (wid ? wsum[wid - 1] : 0);
    if (t < nb) g_boff[t] = incl - v;
}

__global__ void scatter_kernel(const int* __restrict__ ei, int e) {
    int i = blockIdx.x * blockDim.x + threadIdx.x;
    if (i < e) {
        int s = ei[i];
        int d = ei[e + i];
        int base = g_fillbase[d] + g_boff[d >> 10];
        int pos = base + atomicAdd(&g_cnt2[d], 1);
        g_srcs[pos] = s;
    }
}

// ---------------- GEMM1 (wmma) + att1 fold ------------------------------------
// block tile M=64, N=128, K-chunks of 32. 256 threads = 8 warps.
// warp w: frag rows (w>>1)*16, frag cols (w&1)*64 (4 n-frags).
__global__ void gemm1_kernel(const float* __restrict__ A, const float* __restrict__ B,
                             const float* __restrict__ att_s, const float* __restrict__ att_d,
                             int M) {
    __shared__ __half sA[64 * 40];
    __shared__ __half sB[32 * 136];
    __shared__ float  sC[64 * 132];
    int tid = threadIdx.x;
    int wid = tid >> 5;
    int row0 = blockIdx.x * 64;
    int mr = (wid >> 1) * 16;
    int nc = (wid & 1) * 64;

    wmma::fragment<wmma::accumulator, 16, 16, 16, float> cf[4];
    #pragma unroll
    for (int j = 0; j < 4; j++) wmma::fill_fragment(cf[j], 0.f);

    int ar = tid >> 2;
    int ac = (tid & 3) * 8;
    int br = tid >> 3;
    int bc = (tid & 7) * 16;

    for (int k0 = 0; k0 < 256; k0 += 32) {
        int grow = row0 + ar;
        float4 v0;
        float4 v1;
        if (grow < M) {
            const float4* ap = (const float4*)(A + (size_t)grow * 256 + k0 + ac);
            v0 = ap[0];
            v1 = ap[1];
        } else {
            v0 = make_float4(0.f, 0.f, 0.f, 0.f);
            v1 = v0;
        }
        __half2* adst = (__half2*)&sA[ar * 40 + ac];
        adst[0] = __floats2half2_rn(v0.x, v0.y);
        adst[1] = __floats2half2_rn(v0.z, v0.w);
        adst[2] = __floats2half2_rn(v1.x, v1.y);
        adst[3] = __floats2half2_rn(v1.z, v1.w);

        const float4* bp = (const float4*)(B + (size_t)(k0 + br) * 128 + bc);
        float4 w0 = bp[0];
        float4 w1 = bp[1];
        float4 w2 = bp[2];
        float4 w3 = bp[3];
        __half2* bdst = (__half2*)&sB[br * 136 + bc];
        bdst[0] = __floats2half2_rn(w0.x, w0.y);
        bdst[1] = __floats2half2_rn(w0.z, w0.w);
        bdst[2] = __floats2half2_rn(w1.x, w1.y);
        bdst[3] = __floats2half2_rn(w1.z, w1.w);
        bdst[4] = __floats2half2_rn(w2.x, w2.y);
        bdst[5] = __floats2half2_rn(w2.z, w2.w);
        bdst[6] = __floats2half2_rn(w3.x, w3.y);
        bdst[7] = __floats2half2_rn(w3.z, w3.w);
        __syncthreads();

        #pragma unroll
        for (int kk = 0; kk < 32; kk += 16) {
            wmma::fragment<wmma::matrix_a, 16, 16, 16, __half, wmma::row_major> af;
            wmma::load_matrix_sync(af, &sA[mr * 40 + kk], 40);
            #pragma unroll
            for (int j = 0; j < 4; j++) {
                wmma::fragment<wmma::matrix_b, 16, 16, 16, __half, wmma::row_major> bf;
                wmma::load_matrix_sync(bf, &sB[kk * 136 + nc + j * 16], 136);
                wmma::mma_sync(cf[j], af, bf, cf[j]);
            }
        }
        __syncthreads();
    }

    #pragma unroll
    for (int j = 0; j < 4; j++) {
        wmma::store_matrix_sync(&sC[mr * 132 + nc + j * 16], cf[j], 132, wmma::mem_row_major);
    }
    __syncthreads();

    // epilogue: thread owns row tid>>2, cols (tid&3)*32..+31 = heads 2c, 2c+1
    int erow = tid >> 2;
    int ec = tid & 3;
    int grow = row0 + erow;
    if (grow < M) {
        int col0 = ec * 32;
        float vals[32];
        #pragma unroll
        for (int j = 0; j < 32; j++) vals[j] = sC[erow * 132 + col0 + j];
        __half2 hv[16];
        #pragma unroll
        for (int j = 0; j < 16; j++) hv[j] = __floats2half2_rn(vals[2 * j], vals[2 * j + 1]);
        uint4* hdst = (uint4*)&g_h1h[(size_t)grow * 128 + col0];
        hdst[0] = *(uint4*)&hv[0];
        hdst[1] = *(uint4*)&hv[4];
        hdst[2] = *(uint4*)&hv[8];
        hdst[3] = *(uint4*)&hv[12];
        #pragma unroll
        for (int hh = 0; hh < 2; hh++) {
            int head = 2 * ec + hh;
            float ssum = 0.f;
            float dsum = 0.f;
            #pragma unroll
            for (int j = 0; j < 16; j++) {
                float vv = vals[hh * 16 + j];
                ssum += vv * __ldg(&att_s[head * 16 + j]);
                dsum += vv * __ldg(&att_d[head * 16 + j]);
            }
            g_as1[grow * 8 + head] = ssum;
            g_ad1[grow * 8 + head] = dsum;
        }
    }
}

// ---------------- layer-1 gather (warp per node) ------------------------------
__global__ void gat1_kernel(const float* __restrict__ b1, int n) {
    int node = (blockIdx.x * blockDim.x + threadIdx.x) >> 5;
    int lid = threadIdx.x & 31;
    if (node >= n) return;
    int beg = g_fillbase[node] + g_boff[node >> 10];
    int end = beg + g_cnt2[node];

    int h = lid >> 2;
    int eo = lid >> 3;
    int hh = lid & 7;
    float adl = g_ad1[node * 8 + hh];
    float4 acc = make_float4(0.f, 0.f, 0.f, 0.f);
    float dpart = 0.f;

    for (int base = beg; base < end; base += 32) {
        int cnt = end - base;
        if (cnt > 32) cnt = 32;
        int sidx = (base + lid < end) ? __ldg(&g_srcs[base + lid]) : 0;
        for (int g = 0; g < cnt; g += 4) {
            int sj = __shfl_sync(0xffffffffu, sidx, g + eo);
            float w = 0.f;
            if (g + eo < cnt) w = __expf(lrelu(__ldg(&g_as1[sj * 8 + hh]) + adl));
            dpart += w;
            #pragma unroll
            for (int q = 0; q < 4; q++) {
                float wq = __shfl_sync(0xffffffffu, w, q * 8 + h);
                int sq = __shfl_sync(0xffffffffu, sidx, g + q);
                uint2 hvv = *(const uint2*)&g_h1h[(size_t)sq * 128 + lid * 4];
                float2 f0 = __half22float2(*(__half2*)&hvv.x);
                float2 f1 = __half22float2(*(__half2*)&hvv.y);
                acc.x += wq * f0.x;
                acc.y += wq * f0.y;
                acc.z += wq * f1.x;
                acc.w += wq * f1.y;
            }
        }
    }
    float dsum = dpart;
    dsum += __shfl_xor_sync(0xffffffffu, dsum, 8);
    dsum += __shfl_xor_sync(0xffffffffu, dsum, 16);
    float dh = __shfl_sync(0xffffffffu, dsum, h);
    float inv = 1.f / (dh + 1e-16f);
    float4 bb = *(const float4*)&b1[lid * 4];
    __half2 o0 = __floats2half2_rn(elu1(acc.x * inv + bb.x), elu1(acc.y * inv + bb.y));
    __half2 o1 = __floats2half2_rn(elu1(acc.z * inv + bb.z), elu1(acc.w * inv + bb.w));
    uint2 pk;
    pk.x = *(unsigned int*)&o0;
    pk.y = *(unsigned int*)&o1;
    *(uint2*)&g_x2h[(size_t)node * 128 + lid * 4] = pk;
    if (lid == 0) g_cnt[node] = 0;
}

// ---------------- GEMM2 (wmma) + att2 fold ------------------------------------
// block tile M=64, N=64, K=128 in chunks of 32. warp w: mr=(w>>1)*16, nc=(w&1)*32.
__global__ void gemm2_kernel(const float* __restrict__ B,
                             const float* __restrict__ att_s, const float* __restrict__ att_d,
                             int M) {
    __shared__ __half tA[64 * 40];
    __shared__ __half tB[32 * 72];
    __shared__ float  tC[64 * 68];
    int tid = threadIdx.x;
    int wid = tid >> 5;
    int row0 = blockIdx.x * 64;
    int mr = (wid >> 1) * 16;
    int nc = (wid & 1) * 32;

    wmma::fragment<wmma::accumulator, 16, 16, 16, float> cf[2];
    wmma::fill_fragment(cf[0], 0.f);
    wmma::fill_fragment(cf[1], 0.f);

    int ar = tid >> 2;
    int ac = (tid & 3) * 8;
    int br = tid >> 3;
    int bc = (tid & 7) * 8;

    for (int k0 = 0; k0 < 128; k0 += 32) {
        int grow = row0 + ar;
        uint4 av;
        if (grow < M) {
            av = *(const uint4*)&g_x2h[(size_t)grow * 128 + k0 + ac];
        } else {
            av = make_uint4(0u, 0u, 0u, 0u);
        }
        *(uint4*)&tA[ar * 40 + ac] = av;

        const float4* bp = (const float4*)(B + (size_t)(k0 + br) * 64 + bc);
        float4 w0 = bp[0];
        float4 w1 = bp[1];
        __half2* bdst = (__half2*)&tB[br * 72 + bc];
        bdst[0] = __floats2half2_rn(w0.x, w0.y);
        bdst[1] = __floats2half2_rn(w0.z, w0.w);
        bdst[2] = __floats2half2_rn(w1.x, w1.y);
        bdst[3] = __floats2half2_rn(w1.z, w1.w);
        __syncthreads();

        #pragma unroll
        for (int kk = 0; kk < 32; kk += 16) {
            wmma::fragment<wmma::matrix_a, 16, 16, 16, __half, wmma::row_major> af;
            wmma::load_matrix_sync(af, &tA[mr * 40 + kk], 40);
            #pragma unroll
            for (int j = 0; j < 2; j++) {
                wmma::fragment<wmma::matrix_b, 16, 16, 16, __half, wmma::row_major> bf;
                wmma::load_matrix_sync(bf, &tB[kk * 72 + nc + j * 16], 72);
                wmma::mma_sync(cf[j], af, bf, cf[j]);
            }
        }
        __syncthreads();
    }

    wmma::store_matrix_sync(&tC[mr * 68 + nc], cf[0], 68, wmma::mem_row_major);
    wmma::store_matrix_sync(&tC[mr * 68 + nc + 16], cf[1], 68, wmma::mem_row_major);
    __syncthreads();

    // epilogue: thread owns row tid>>2, cols (tid&3)*16..+15
    int erow = tid >> 2;
    int ec = tid & 3;
    int grow = row0 + erow;
    float ssum = 0.f;
    float dsum = 0.f;
    if (grow < M) {
        int col0 = ec * 16;
        float vals[16];
        #pragma unroll
        for (int j = 0; j < 16; j++) vals[j] = tC[erow * 68 + col0 + j];
        __half2 hv[8];
        #pragma unroll
        for (int j = 0; j < 8; j++) hv[j] = __floats2half2_rn(vals[2 * j], vals[2 * j + 1]);
        uint4* hdst = (uint4*)&g_h2h[(size_t)grow * 64 + col0];
        hdst[0] = *(uint4*)&hv[0];
        hdst[1] = *(uint4*)&hv[4];
        #pragma unroll
        for (int j = 0; j < 16; j++) {
            float vv = vals[j];
            ssum += vv * __ldg(&att_s[col0 + j]);
            dsum += vv * __ldg(&att_d[col0 + j]);
        }
    }
    ssum += __shfl_xor_sync(0xffffffffu, ssum, 1);
    ssum += __shfl_xor_sync(0xffffffffu, ssum, 2);
    dsum += __shfl_xor_sync(0xffffffffu, dsum, 1);
    dsum += __shfl_xor_sync(0xffffffffu, dsum, 2);
    if (ec == 0 && grow < M) {
        g_as2[grow] = ssum;
        g_ad2[grow] = dsum;
    }
}

// ---------------- layer-2 gather + log_softmax --------------------------------
__global__ void gat2_kernel(const float* __restrict__ b2, float* __restrict__ out, int n) {
    int node = (blockIdx.x * blockDim.x + threadIdx.x) >> 5;
    int lid = threadIdx.x & 31;
    if (node >= n) return;
    int beg = g_fillbase[node] + g_boff[node >> 10];
    int end = beg + g_cnt2[node];
    float adn = g_ad2[node];

    float acc0 = 0.f;
    float acc1 = 0.f;
    float dpart = 0.f;
    for (int base = beg; base < end; base += 32) {
        int cnt = end - base;
        if (cnt > 32) cnt = 32;
        int sidx = (base + lid < end) ? __ldg(&g_srcs[base + lid]) : 0;
        for (int g = 0; g < cnt; g += 4) {
            int widx = g + (lid & 3);
            if (widx > 31) widx = 31;
            int sj = __shfl_sync(0xffffffffu, sidx, widx);
            float w = 0.f;
            if (lid < 4 && g + lid < cnt) w = __expf(lrelu(__ldg(&g_as2[sj]) + adn));
            dpart += w;
            #pragma unroll
            for (int q = 0; q < 4; q++) {
                float wq = __shfl_sync(0xffffffffu, w, q);
                int sq = __shfl_sync(0xffffffffu, sidx, g + q);
                __half2 hvv = *(const __half2*)&g_h2h[(size_t)sq * 64 + lid * 2];
                float2 v = __half22float2(hvv);
                acc0 += wq * v.x;
                acc1 += wq * v.y;
            }
        }
    }
    float dsum = dpart;
    dsum += __shfl_xor_sync(0xffffffffu, dsum, 1);
    dsum += __shfl_xor_sync(0xffffffffu, dsum, 2);
    float dt = __shfl_sync(0xffffffffu, dsum, 0);
    float inv = 1.f / (dt + 1e-16f);
    float o0 = acc0 * inv + __ldg(&b2[lid * 2]);
    float o1 = acc1 * inv + __ldg(&b2[lid * 2 + 1]);

    float rm = fmaxf(o0, o1);
    #pragma unroll
    for (int off = 16; off; off >>= 1) rm = fmaxf(rm, __shfl_xor_sync(0xffffffffu, rm, off));
    float se = __expf(o0 - rm) + __expf(o1 - rm);
    #pragma unroll
    for (int off = 16; off; off >>= 1) se += __shfl_xor_sync(0xffffffffu, se, off);
    float lse = rm + __logf(se);

    float2 res;
    res.x = o0 - lse;
    res.y = o1 - lse;
    *(float2*)&out[(size_t)node * 64 + lid * 2] = res;
    if (lid == 0) g_cnt2[node] = 0;
}

// ---------------- launch ------------------------------------------------------
extern "C" void kernel_launch(void* const* d_in, const int* in_sizes, int n_in,
                              void* d_out, int out_size) {
    const float* x      = (const float*)d_in[0];
    const int*   ei     = (const int*)d_in[1];
    const float* W1     = (const float*)d_in[2];
    const float* att1_s = (const float*)d_in[3];
    const float* att1_d = (const float*)d_in[4];
    const float* b1     = (const float*)d_in[5];
    const float* W2     = (const float*)d_in[6];
    const float* att2_s = (const float*)d_in[7];
    const float* att2_d = (const float*)d_in[8];
    const float* b2     = (const float*)d_in[9];
    float* out = (float*)d_out;

    int n = in_sizes[0] / 256;
    int e = in_sizes[1] / 2;
    int nb = (n + 1023) / 1024;

    static cudaStream_t s2 = nullptr;
    static cudaEvent_t evFork = nullptr;
    static cudaEvent_t evJoin = nullptr;
    if (!s2) {
        cudaStreamCreateWithFlags(&s2, cudaStreamNonBlocking);
        cudaEventCreateWithFlags(&evFork, cudaEventDisableTiming);
        cudaEventCreateWithFlags(&evJoin, cudaEventDisableTiming);
    }

    cudaEventRecord(evFork, 0);
    cudaStreamWaitEvent(s2, evFork, 0);
    gemm1_kernel<<<(n + 63) / 64, 256, 0, s2>>>(x, W1, att1_s, att1_d, n);
    cudaEventRecord(evJoin, s2);

    hist_kernel<<<(e + 255) / 256, 256>>>(ei, e);
    scan1_kernel<<<nb, 1024>>>(n);
    scan2_kernel<<<1, 512>>>(nb);
    scatter_kernel<<<(e + 255) / 256, 256>>>(ei, e);

    cudaStreamWaitEvent(0, evJoin, 0);
    gat1_kernel<<<(n + 7) / 8, 256>>>(b1, n);
    gemm2_kernel<<<(n + 63) / 64, 256>>>(W2, att2_s, att2_d, n);
    gat2_kernel<<<(n + 7) / 8, 256>>>(b2, out, n);
}